// round 8
// baseline (speedup 1.0000x reference)
#include <cuda_runtime.h>

#define KSZ 3
#define IN_C 32
#define OUT_C 64
#define HH 256
#define WW 256
#define NB 2
#define KK 9                      // KSZ*KSZ
#define KTOT (3 * IN_C * KK)      // 864 (3 weight sets x 32 ch x 9 positions)
#define KC 32                     // k-chunk
#define NCHUNK (KTOT / KC)        // 27

// Pre-transposed weights, k-major: g_W[k*64 + o], k = t*288 + c*9 + p
__device__ __align__(16) float g_W[KTOT * OUT_C];
// Per-k LUT: .x = xs index base (c*120 + dy*12 + dx), .y = mask row base ((t*9+p)*64)
__device__ ushort2 g_LUT[KTOT];

__global__ void setup_kernel(const float* __restrict__ w0,
                             const float* __restrict__ w1,
                             const float* __restrict__ w2) {
    int idx = blockIdx.x * blockDim.x + threadIdx.x;
    if (idx >= KTOT * OUT_C) return;
    int k = idx >> 6;
    int o = idx & 63;
    int t = k / (IN_C * KK);
    int rem = k - t * (IN_C * KK);          // rem = c*9 + p == flat (c,i,j)
    const float* w = (t == 0) ? w0 : (t == 1) ? w1 : w2;
    g_W[k * OUT_C + o] = w[o * (IN_C * KK) + rem];
    if (o == 0) {
        int c = rem / 9;
        int p = rem - c * 9;
        int dy = p / 3, dx = p - dy * 3;
        g_LUT[k] = make_ushort2((unsigned short)(c * 120 + dy * 12 + dx),
                                (unsigned short)((t * 9 + p) * 64));
    }
}

// Block: 128 threads, computes 64 outch x 64 pixels (8x8 spatial tile).
// Thread micro-tile: 4 outch x 8 pixels (32 fp32 accumulators).
__global__ __launch_bounds__(128, 5)
void conv25d_kernel(const float* __restrict__ x,
                    const float* __restrict__ disp,
                    const float* __restrict__ fx,
                    const float* __restrict__ baseline,
                    float* __restrict__ out) {
    __shared__ float xs[IN_C * 120];             // x tile + halo: [c][10][12]
    __shared__ float dsh[120];                   // disp tile + halo
    __shared__ float msk[27 * 64];               // [(t*9+p)][pix]
    __shared__ __align__(16) float As[KC * 64];  // weights [kk][o]
    __shared__ __align__(16) float Bs[KC * 64];  // masked x [kk][pix]
    __shared__ ushort2 lut[KTOT];

    const int tid = threadIdx.x;
    const int n  = blockIdx.z;
    const int x0 = blockIdx.x * 8;
    const int y0 = blockIdx.y * 8;

    const float fxv = fx[n];
    const float bfx = __fmul_rn(baseline[n], fxv);

    // ---- load per-k LUT ----
    for (int i = tid; i < KTOT; i += 128) lut[i] = g_LUT[i];

    // ---- load disp tile (10x10 with halo, zero-padded OOB) ----
    const float* dbase = disp + (size_t)n * (HH * WW);
    for (int i = tid; i < 100; i += 128) {
        int yy = i / 10, xx = i - yy * 10;
        int gy = y0 + yy - 1, gx = x0 + xx - 1;
        float v = 0.f;
        if (gy >= 0 && gy < HH && gx >= 0 && gx < WW) v = dbase[gy * WW + gx];
        dsh[yy * 12 + xx] = v;
    }
    // ---- load x tile (32 x 10 x 10 with halo) ----
    const float* xbase = x + (size_t)n * (IN_C * HH * WW);
    for (int i = tid; i < IN_C * 100; i += 128) {
        int c = i / 100; int rem = i - c * 100;
        int yy = rem / 10, xx = rem - yy * 10;
        int gy = y0 + yy - 1, gx = x0 + xx - 1;
        float v = 0.f;
        if (gy >= 0 && gy < HH && gx >= 0 && gx < WW)
            v = xbase[(size_t)c * (HH * WW) + gy * WW + gx];
        xs[c * 120 + yy * 12 + xx] = v;
    }
    __syncthreads();

    // ---- masks: per (pixel, kernel position) -> m0, m1, m2 ----
    // IEEE-RN intrinsics mirror the reference fp32 math exactly, independent
    // of --use_fast_math. grid_range/2 is exact in fp32.
    for (int i = tid; i < 576; i += 128) {
        int pix = i / 9, p = i - pix * 9;
        int ty = pix >> 3, tx = pix & 7;
        float dc = dsh[(ty + 1) * 12 + tx + 1];
        float vc = (dc != 0.f) ? 1.f : 0.f;
        float cd = __fdiv_rn(bfx, fminf(fmaxf(__fmul_rn(dc, vc), 0.01f), 256.f));
        float gr = __fdiv_rn(__fmul_rn(16.f, cd), fxv);
        float hf = 0.5f * gr;
        int dy = p / 3, dx = p - dy * 3;
        float d = dsh[(ty + dy) * 12 + tx + dx];
        float v = ((d != 0.f) ? 1.f : 0.f) * vc;
        float de = __fdiv_rn(bfx, fminf(fmaxf(__fmul_rn(d, v), 0.01f), 256.f));
        float m0 = (fabsf(de - (cd + gr)) <= hf) ? 1.f : 0.f;
        float m1 = (fabsf(de - cd)        <= hf) ? 1.f : 0.f;
        m1 = fminf(m1 + 1.f - v, 1.f);   // clip(m1 + 1 - valid, 0, 1); term >= 0 always
        float m2 = (fabsf(de - (cd - gr)) <= hf) ? 1.f : 0.f;
        msk[(0 * 9 + p) * 64 + pix] = m0;
        msk[(1 * 9 + p) * 64 + pix] = m1;
        msk[(2 * 9 + p) * 64 + pix] = m2;
    }

    // ---- GEMM thread mapping ----
    const int o4   = (tid & 15) * 4;   // 4 output channels
    const int pg   = tid >> 4;         // pixel row within 8x8 tile (0..7)
    const int pix8 = pg * 8;           // 8 pixels (one tile row)

    // B-staging mapping: each thread owns one pixel column, 2 rows stride
    const int pix_s = tid & 63;
    const int r0    = tid >> 6;                        // 0 or 1
    const int sbase = (pix_s >> 3) * 12 + (pix_s & 7); // xs offset of this pixel

    // A prefetch mapping: thread covers quarter-row of the [32][64] chunk
    const int aRow  = tid >> 2;        // 0..31
    const int aCol4 = (tid & 3) * 4;   // float4 index within 16-float4 row

    float4 aPre[4];
    {
        const float4* src = (const float4*)g_W + (size_t)aRow * 16 + aCol4;
        aPre[0] = src[0]; aPre[1] = src[1]; aPre[2] = src[2]; aPre[3] = src[3];
    }

    float acc[4][8];
    #pragma unroll
    for (int io = 0; io < 4; io++)
        #pragma unroll
        for (int ip = 0; ip < 8; ip++) acc[io][ip] = 0.f;

    __syncthreads();  // xs + msk + lut ready

    for (int ch = 0; ch < NCHUNK; ch++) {
        // store prefetched A chunk
        {
            float4* dst = (float4*)As + (size_t)aRow * 16 + aCol4;
            dst[0] = aPre[0]; dst[1] = aPre[1]; dst[2] = aPre[2]; dst[3] = aPre[3];
        }
        // stage masked-B chunk: Bs[r][pix] = x_col * mask  (LUT-driven)
        #pragma unroll
        for (int i = 0; i < 16; i++) {
            int r = r0 + 2 * i;
            ushort2 e = lut[ch * KC + r];
            float xv = xs[(int)e.x + sbase];
            Bs[r * 64 + pix_s] = xv * msk[(int)e.y + pix_s];
        }
        __syncthreads();

        // prefetch next A chunk (L2-resident; latency hidden by FMA loop)
        if (ch + 1 < NCHUNK) {
            const float4* src = (const float4*)g_W
                              + ((size_t)(ch + 1) * KC + aRow) * 16 + aCol4;
            aPre[0] = src[0]; aPre[1] = src[1]; aPre[2] = src[2]; aPre[3] = src[3];
        }

        // micro-GEMM: 32 k-steps x (4 o x 8 pix)
        #pragma unroll 8
        for (int kk = 0; kk < KC; kk++) {
            float4 a  = *(const float4*)&As[kk * 64 + o4];
            float4 b0 = *(const float4*)&Bs[kk * 64 + pix8];
            float4 b1 = *(const float4*)&Bs[kk * 64 + pix8 + 4];
            acc[0][0] += a.x * b0.x; acc[0][1] += a.x * b0.y;
            acc[0][2] += a.x * b0.z; acc[0][3] += a.x * b0.w;
            acc[0][4] += a.x * b1.x; acc[0][5] += a.x * b1.y;
            acc[0][6] += a.x * b1.z; acc[0][7] += a.x * b1.w;
            acc[1][0] += a.y * b0.x; acc[1][1] += a.y * b0.y;
            acc[1][2] += a.y * b0.z; acc[1][3] += a.y * b0.w;
            acc[1][4] += a.y * b1.x; acc[1][5] += a.y * b1.y;
            acc[1][6] += a.y * b1.z; acc[1][7] += a.y * b1.w;
            acc[2][0] += a.z * b0.x; acc[2][1] += a.z * b0.y;
            acc[2][2] += a.z * b0.z; acc[2][3] += a.z * b0.w;
            acc[2][4] += a.z * b1.x; acc[2][5] += a.z * b1.y;
            acc[2][6] += a.z * b1.z; acc[2][7] += a.z * b1.w;
            acc[3][0] += a.w * b0.x; acc[3][1] += a.w * b0.y;
            acc[3][2] += a.w * b0.z; acc[3][3] += a.w * b0.w;
            acc[3][4] += a.w * b1.x; acc[3][5] += a.w * b1.y;
            acc[3][6] += a.w * b1.z; acc[3][7] += a.w * b1.w;
        }
        __syncthreads();
    }

    // ---- epilogue: out[n][o][y0+pg][x0 + 0..7] ----
    float* obase = out + (size_t)n * OUT_C * HH * WW;
    const int gy = y0 + pg;
    #pragma unroll
    for (int io = 0; io < 4; io++) {
        int o = o4 + io;
        float* po = obase + ((size_t)o * HH + gy) * WW + x0;
        *(float4*)po       = make_float4(acc[io][0], acc[io][1], acc[io][2], acc[io][3]);
        *(float4*)(po + 4) = make_float4(acc[io][4], acc[io][5], acc[io][6], acc[io][7]);
    }
}

extern "C" void kernel_launch(void* const* d_in, const int* in_sizes, int n_in,
                              void* d_out, int out_size) {
    const float* x    = (const float*)d_in[0];
    const float* disp = (const float*)d_in[1];
    const float* fx   = (const float*)d_in[2];
    const float* bl   = (const float*)d_in[3];
    const float* w0   = (const float*)d_in[4];
    const float* w1   = (const float*)d_in[5];
    const float* w2   = (const float*)d_in[6];

    setup_kernel<<<(KTOT * OUT_C + 255) / 256, 256>>>(w0, w1, w2);

    dim3 grid(WW / 8, HH / 8, NB);
    conv25d_kernel<<<grid, 128>>>(x, disp, fx, bl, (float*)d_out);
}